// round 3
// baseline (speedup 1.0000x reference)
#include <cuda_runtime.h>
#include <cstdint>

// ---------------------------------------------------------------------------
// SparseResBlock: h = ReLU(BN1(spconv(x,W1,nbr1)));
//                 h = BN2(spconv(h,W2,nbr2));
//                 out = ReLU(h + BNd(x @ Wd))
// N=200000, Cin=64, Cout=128, K=27. BN uses batch statistics over all N rows.
// ---------------------------------------------------------------------------

#define EPS_BN 1e-5f

constexpr int COUT   = 128;
constexpr int ROWS   = 64;      // rows per CTA tile
constexpr int NTH    = 256;     // threads per CTA
constexpr int MAXN   = 200000;
constexpr int MAXBLK = (MAXN + ROWS - 1) / ROWS;   // 3125

// Scratch (device globals: allocation inside kernel_launch is forbidden)
__device__ float g_h1[(size_t)MAXN * COUT];   // conv1 raw output
__device__ float g_h2[(size_t)MAXN * COUT];   // conv2 raw output
__device__ float g_sk[(size_t)MAXN * COUT];   // skip raw output
__device__ float g_part1[(size_t)MAXBLK * 256];
__device__ float g_part2[(size_t)MAXBLK * 256];
__device__ float g_partd[(size_t)MAXBLK * 256];
__device__ float g_sc1[COUT], g_sh1[COUT];
__device__ float g_sc2[COUT], g_sh2[COUT];
__device__ float g_scd[COUT], g_shd[COUT];

// ---------------------------------------------------------------------------
// Gather-GEMM: out[base..base+63, 0..127] = sum_k gather_k(feats) @ W[k]
//   feats: [n, CIN], W: [K, CIN, COUT], nbr: [K, n] (-1 = missing; nullptr =>
//   identity gather). TRANS applies y = relu(x*tsc + tsh) during the gather
//   (used by conv2 to consume BN1+ReLU-transformed h1 without an extra pass).
// Also emits per-channel partial sums (Sx, Sx^2) for downstream batchnorm.
// Thread layout: cg = tid&31 -> 4 output cols; rg = tid>>5 -> 8 output rows.
// ---------------------------------------------------------------------------
template<int CIN, bool TRANS>
__global__ __launch_bounds__(NTH, 2)
void conv_kernel(const float* __restrict__ feats,
                 const float* __restrict__ W,
                 const int*   __restrict__ nbr,
                 int K, int n,
                 const float* __restrict__ tsc,
                 const float* __restrict__ tsh,
                 float* __restrict__ out,
                 float* __restrict__ partial)
{
    __shared__ float sA[ROWS * CIN];

    const int tid  = threadIdx.x;
    const int cg   = tid & 31;     // column group: cols cg*4 .. cg*4+3
    const int rg   = tid >> 5;     // row group:    rows rg*8 .. rg*8+7
    const int base = blockIdx.x * ROWS;

    float acc[8][4];
#pragma unroll
    for (int i = 0; i < 8; ++i)
#pragma unroll
        for (int j = 0; j < 4; ++j) acc[i][j] = 0.0f;

    constexpr int V = CIN / 4;     // float4 per row

    for (int k = 0; k < K; ++k) {
        __syncthreads();
        // ---- masked gather of 64 rows into SMEM (zero rows for idx < 0) ----
        for (int e = tid; e < ROWS * V; e += NTH) {
            const int r   = e / V;
            const int c4  = e - r * V;
            const int row = base + r;
            int idx = -1;
            if (row < n)
                idx = nbr ? __ldg(&nbr[(size_t)k * n + row]) : row;
            float4 v = make_float4(0.f, 0.f, 0.f, 0.f);
            if (idx >= 0) {
                v = reinterpret_cast<const float4*>(feats)[(size_t)idx * V + c4];
                if (TRANS) {
                    const float4 sc = reinterpret_cast<const float4*>(tsc)[c4];
                    const float4 sh = reinterpret_cast<const float4*>(tsh)[c4];
                    v.x = fmaxf(0.f, fmaf(v.x, sc.x, sh.x));
                    v.y = fmaxf(0.f, fmaf(v.y, sc.y, sh.y));
                    v.z = fmaxf(0.f, fmaf(v.z, sc.z, sh.z));
                    v.w = fmaxf(0.f, fmaf(v.w, sc.w, sh.w));
                }
            }
            reinterpret_cast<float4*>(sA)[e] = v;
        }
        __syncthreads();

        // ---- rank-1 update loop: A from SMEM (broadcast), W from L1/L2 ----
        const float4* Wk = reinterpret_cast<const float4*>(W)
                         + (size_t)k * CIN * (COUT / 4);
#pragma unroll 4
        for (int cc = 0; cc < CIN; ++cc) {
            const float4 b = __ldg(&Wk[cc * (COUT / 4) + cg]);
#pragma unroll
            for (int i = 0; i < 8; ++i) {
                const float a = sA[(rg * 8 + i) * CIN + cc];
                acc[i][0] = fmaf(a, b.x, acc[i][0]);
                acc[i][1] = fmaf(a, b.y, acc[i][1]);
                acc[i][2] = fmaf(a, b.z, acc[i][2]);
                acc[i][3] = fmaf(a, b.w, acc[i][3]);
            }
        }
    }

    // ---- store raw conv output ----
#pragma unroll
    for (int i = 0; i < 8; ++i) {
        const int row = base + rg * 8 + i;
        if (row < n) {
            const float4 v = make_float4(acc[i][0], acc[i][1], acc[i][2], acc[i][3]);
            reinterpret_cast<float4*>(out)[(size_t)row * (COUT / 4) + cg] = v;
        }
    }

    // ---- deterministic per-channel partial reduction (Sx | Sx^2) ----
    float s[4], q[4];
#pragma unroll
    for (int j = 0; j < 4; ++j) { s[j] = 0.f; q[j] = 0.f; }
#pragma unroll
    for (int i = 0; i < 8; ++i)
#pragma unroll
        for (int j = 0; j < 4; ++j) {
            const float v = acc[i][j];
            s[j] += v;
            q[j] += v * v;
        }

    __syncthreads();                    // done with sA gather contents
    float* red = sA;                    // reuse: needs 8*256 floats <= ROWS*CIN
#pragma unroll
    for (int j = 0; j < 4; ++j) {
        red[rg * 256 + cg * 4 + j]       = s[j];
        red[rg * 256 + 128 + cg * 4 + j] = q[j];
    }
    __syncthreads();
    float tot = 0.f;
#pragma unroll
    for (int w = 0; w < 8; ++w) tot += red[w * 256 + tid];
    partial[(size_t)blockIdx.x * 256 + tid] = tot;
}

// ---------------------------------------------------------------------------
// Fold partials into per-channel (scale, shift): y = x*scale + shift
// where scale = gamma * rsqrt(var+eps), shift = beta - mean*scale.
// ---------------------------------------------------------------------------
__global__ void bn_finalize(const float* __restrict__ partial, int nb, int n,
                            const float* __restrict__ gamma,
                            const float* __restrict__ beta,
                            float* __restrict__ scale,
                            float* __restrict__ shift)
{
    const int c = threadIdx.x;
    if (c >= COUT) return;
    double S = 0.0, Q = 0.0;
    for (int b = 0; b < nb; ++b) {
        S += (double)partial[(size_t)b * 256 + c];
        Q += (double)partial[(size_t)b * 256 + 128 + c];
    }
    const double mean = S / n;
    const double var  = Q / n - mean * mean;
    const float  r    = rsqrtf((float)var + EPS_BN);
    const float  sc   = gamma[c] * r;
    scale[c] = sc;
    shift[c] = beta[c] - (float)mean * sc;
}

// ---------------------------------------------------------------------------
// out = relu( h2*sc2 + sh2 + sk*scd + shd )   (float4 elementwise)
// ---------------------------------------------------------------------------
__global__ void final_kernel(const float* __restrict__ h2,
                             const float* __restrict__ sk,
                             const float* __restrict__ sc2,
                             const float* __restrict__ sh2,
                             const float* __restrict__ scd,
                             const float* __restrict__ shd,
                             float* __restrict__ out, int total4)
{
    const int i = blockIdx.x * blockDim.x + threadIdx.x;
    if (i >= total4) return;
    const int c4 = i & 31;
    const float4 a  = reinterpret_cast<const float4*>(h2)[i];
    const float4 b  = reinterpret_cast<const float4*>(sk)[i];
    const float4 s2 = reinterpret_cast<const float4*>(sc2)[c4];
    const float4 t2 = reinterpret_cast<const float4*>(sh2)[c4];
    const float4 sd = reinterpret_cast<const float4*>(scd)[c4];
    const float4 td = reinterpret_cast<const float4*>(shd)[c4];
    float4 v;
    v.x = fmaxf(0.f, fmaf(a.x, s2.x, t2.x) + fmaf(b.x, sd.x, td.x));
    v.y = fmaxf(0.f, fmaf(a.y, s2.y, t2.y) + fmaf(b.y, sd.y, td.y));
    v.z = fmaxf(0.f, fmaf(a.z, s2.z, t2.z) + fmaf(b.z, sd.z, td.z));
    v.w = fmaxf(0.f, fmaf(a.w, s2.w, t2.w) + fmaf(b.w, sd.w, td.w));
    reinterpret_cast<float4*>(out)[i] = v;
}

// ---------------------------------------------------------------------------
extern "C" void kernel_launch(void* const* d_in, const int* in_sizes, int n_in,
                              void* d_out, int out_size)
{
    const float* feats = (const float*)d_in[0];
    const int*   nbr1  = (const int*)  d_in[1];
    const int*   nbr2  = (const int*)  d_in[2];
    const float* W1    = (const float*)d_in[3];
    const float* W2    = (const float*)d_in[4];
    const float* Wd    = (const float*)d_in[5];
    const float* g1    = (const float*)d_in[6];
    const float* b1    = (const float*)d_in[7];
    const float* g2    = (const float*)d_in[8];
    const float* b2    = (const float*)d_in[9];
    const float* gd    = (const float*)d_in[10];
    const float* bd    = (const float*)d_in[11];
    float* out = (float*)d_out;

    const int n  = in_sizes[0] / 64;      // 200000
    const int K  = in_sizes[1] / n;       // 27
    const int nb = (n + ROWS - 1) / ROWS; // 3125

    float *h1, *h2, *sk, *p1, *p2, *pd;
    float *sc1, *sh1, *sc2, *sh2, *scd, *shd;
    cudaGetSymbolAddress((void**)&h1,  g_h1);
    cudaGetSymbolAddress((void**)&h2,  g_h2);
    cudaGetSymbolAddress((void**)&sk,  g_sk);
    cudaGetSymbolAddress((void**)&p1,  g_part1);
    cudaGetSymbolAddress((void**)&p2,  g_part2);
    cudaGetSymbolAddress((void**)&pd,  g_partd);
    cudaGetSymbolAddress((void**)&sc1, g_sc1);
    cudaGetSymbolAddress((void**)&sh1, g_sh1);
    cudaGetSymbolAddress((void**)&sc2, g_sc2);
    cudaGetSymbolAddress((void**)&sh2, g_sh2);
    cudaGetSymbolAddress((void**)&scd, g_scd);
    cudaGetSymbolAddress((void**)&shd, g_shd);

    // conv1: h1 = spconv(feats, W1, nbr1)        [+ BN1 partials]
    conv_kernel<64, false><<<nb, NTH>>>(feats, W1, nbr1, K, n,
                                        nullptr, nullptr, h1, p1);
    // skip:  sk = feats @ Wd (identity gather)   [+ BNd partials]
    conv_kernel<64, false><<<nb, NTH>>>(feats, Wd, nullptr, 1, n,
                                        nullptr, nullptr, sk, pd);
    // BN1 / BNd scale+shift
    bn_finalize<<<1, 128>>>(p1, nb, n, g1, b1, sc1, sh1);
    bn_finalize<<<1, 128>>>(pd, nb, n, gd, bd, scd, shd);
    // conv2: h2 = spconv(relu(BN1(h1)), W2, nbr2)  (BN1+relu fused in gather)
    conv_kernel<128, true><<<nb, NTH>>>(h1, W2, nbr2, K, n,
                                        sc1, sh1, h2, p2);
    // BN2 scale+shift
    bn_finalize<<<1, 128>>>(p2, nb, n, g2, b2, sc2, sh2);
    // out = relu(BN2(h2) + BNd(sk))
    const int total4 = n * (COUT / 4);
    final_kernel<<<(total4 + NTH - 1) / NTH, NTH>>>(h2, sk, sc2, sh2,
                                                    scd, shd, out, total4);
}

// round 4
// speedup vs baseline: 5.1166x; 5.1166x over previous
#include <cuda_runtime.h>
#include <cstdint>

// ---------------------------------------------------------------------------
// SparseResBlock on sm_103a — tf32 mma.sync tensor-core path.
//   h   = ReLU(BN1(spconv(x, W1, nbr1)))
//   h2  = BN2(spconv(h, W2, nbr2))
//   out = ReLU(h2 + BNd(x @ Wd))
// N=200000 (divisible by 64), Cin=64, Cout=128, K=27.
// ---------------------------------------------------------------------------

#define EPS_BN 1e-5f

constexpr int COUT   = 128;
constexpr int ROWS   = 64;        // output rows per CTA
constexpr int NTH    = 256;       // 8 warps: 4 row-warps x 2 col-warps
constexpr int MAXN   = 200000;
constexpr int MAXBLK = (MAXN + ROWS - 1) / ROWS;   // 3125

// ---- device-global scratch (no allocation allowed in kernel_launch) ----
__device__ float g_h1 [(size_t)MAXN * COUT];  // conv1 raw fp32
__device__ float g_h1t[(size_t)MAXN * COUT];  // relu(BN1(h1)), tf32-rounded
__device__ float g_h2 [(size_t)MAXN * COUT];  // conv2 raw fp32
__device__ float g_sk [(size_t)MAXN * COUT];  // skip raw fp32
__device__ float g_xt [(size_t)MAXN * 64];    // feats, tf32-rounded
__device__ float g_wp1[27 * 64  * 128];       // W1 in mma-fragment order
__device__ float g_wp2[27 * 128 * 128];       // W2 in mma-fragment order
__device__ float g_wpd[64 * 128];             // Wd in mma-fragment order
__device__ float g_part1[(size_t)MAXBLK * 256];
__device__ float g_part2[(size_t)MAXBLK * 256];
__device__ float g_partd[(size_t)MAXBLK * 256];
__device__ float g_sc1[COUT], g_sh1[COUT];
__device__ float g_sc2[COUT], g_sh2[COUT];
__device__ float g_scd[COUT], g_shd[COUT];

// ---------------------------------------------------------------------------
__device__ __forceinline__ float tf32r(float x) {
    uint32_t u;
    asm("cvt.rna.tf32.f32 %0, %1;" : "=r"(u) : "f"(x));
    return __uint_as_float(u);
}

__device__ __forceinline__ void cp16(uint32_t dst, const void* src, int sz) {
    // cp.async 16B with runtime src-size (0 => zero-fill)
    asm volatile("cp.async.cg.shared.global [%0], [%1], 16, %2;\n"
                 :: "r"(dst), "l"(src), "r"(sz));
}
__device__ __forceinline__ void cp_commit() {
    asm volatile("cp.async.commit_group;\n" ::: "memory");
}
__device__ __forceinline__ void cp_wait_all() {
    asm volatile("cp.async.wait_group 0;\n" ::: "memory");
}

__device__ __forceinline__ void mma_tf32(float acc[4],
                                         uint32_t a0, uint32_t a1,
                                         uint32_t a2, uint32_t a3,
                                         uint32_t b0, uint32_t b1) {
    asm volatile(
        "mma.sync.aligned.m16n8k8.row.col.f32.tf32.tf32.f32 "
        "{%0,%1,%2,%3}, {%4,%5,%6,%7}, {%8,%9}, {%0,%1,%2,%3};\n"
        : "+f"(acc[0]), "+f"(acc[1]), "+f"(acc[2]), "+f"(acc[3])
        : "r"(a0), "r"(a1), "r"(a2), "r"(a3), "r"(b0), "r"(b1));
}

// ---------------------------------------------------------------------------
// Weight reorder: W[K][CIN][128] -> fragment order for m16n8k8 .row.col:
//   frag element gid = ((k*KC + kc)*16 + nt)*32 + lane holds float2
//     {W[k][kc*8 + lane%4    ][nt*8 + lane/4],
//      W[k][kc*8 + lane%4 + 4][nt*8 + lane/4]}   (tf32-rounded)
// so a warp's B-frag load is one coalesced 256B LDG.64.
// ---------------------------------------------------------------------------
__global__ void prep_w(const float* __restrict__ W, float* __restrict__ Wp,
                       int K, int CIN)
{
    const int KC    = CIN / 8;
    const int total = K * KC * 16 * 32;
    const int gid   = blockIdx.x * blockDim.x + threadIdx.x;
    if (gid >= total) return;
    const int lane = gid & 31;
    int t  = gid >> 5;
    const int nt = t & 15;  t >>= 4;
    const int kc = t % KC;
    const int k  = t / KC;
    const int row = kc * 8 + (lane & 3);
    const int col = nt * 8 + (lane >> 2);
    const size_t base = ((size_t)k * CIN + row) * COUT + col;
    Wp[(size_t)gid * 2]     = tf32r(W[base]);
    Wp[(size_t)gid * 2 + 1] = tf32r(W[base + 4 * COUT]);
}

// elementwise: y = tf32(x)
__global__ void cvt_kernel(const float* __restrict__ x, float* __restrict__ y,
                           int total4)
{
    const int i = blockIdx.x * blockDim.x + threadIdx.x;
    if (i >= total4) return;
    float4 v = reinterpret_cast<const float4*>(x)[i];
    v.x = tf32r(v.x); v.y = tf32r(v.y); v.z = tf32r(v.z); v.w = tf32r(v.w);
    reinterpret_cast<float4*>(y)[i] = v;
}

// elementwise: y = tf32(relu(x*sc + sh)), per-channel sc/sh (COUT=128)
__global__ void bn_relu_cvt(const float* __restrict__ x,
                            const float* __restrict__ sc,
                            const float* __restrict__ sh,
                            float* __restrict__ y, int total4)
{
    const int i = blockIdx.x * blockDim.x + threadIdx.x;
    if (i >= total4) return;
    const int c4 = i & 31;
    float4 v = reinterpret_cast<const float4*>(x)[i];
    const float4 s = reinterpret_cast<const float4*>(sc)[c4];
    const float4 t = reinterpret_cast<const float4*>(sh)[c4];
    v.x = tf32r(fmaxf(0.f, fmaf(v.x, s.x, t.x)));
    v.y = tf32r(fmaxf(0.f, fmaf(v.y, s.y, t.y)));
    v.z = tf32r(fmaxf(0.f, fmaf(v.z, s.z, t.z)));
    v.w = tf32r(fmaxf(0.f, fmaf(v.w, s.w, t.w)));
    reinterpret_cast<float4*>(y)[i] = v;
}

// ---------------------------------------------------------------------------
// Tensor-core gather-GEMM. CTA: 64 rows x 128 cols. 8 warps; warp (wr,wc)
// owns a 16x64 sub-tile = 8 m16n8k8 mmas. A gathered into double-buffered
// SMEM via cp.async (zero-fill for missing neighbors), B-frags streamed from
// pre-reordered weights. Emits per-channel (Sx, Sx^2) partials for BN.
// SMEM row pad +4 words => frag LDS bank = (4g + tg + c) mod 32: conflict-free.
// ---------------------------------------------------------------------------
template<int CIN>
__global__ __launch_bounds__(NTH, 2)
void conv_mma(const float* __restrict__ X,     // [n, CIN], tf32-rounded
              const float* __restrict__ Wp,    // fragment-ordered weights
              const int*   __restrict__ nbr,   // [K, n] or nullptr (identity)
              int K, int n,
              float* __restrict__ out,         // [n, COUT] fp32
              float* __restrict__ partial)     // [nb, 256] (Sx | Sxx)
{
    constexpr int STRIDE = CIN + 4;            // padded SMEM row (words)
    constexpr int V      = CIN / 4;            // float4 per row
    constexpr int KC     = CIN / 8;            // k-chunks per offset
    extern __shared__ float sA[];              // [2][ROWS*STRIDE]

    const int tid  = threadIdx.x;
    const int lane = tid & 31, warp = tid >> 5;
    const int wr   = warp & 3,  wc  = warp >> 2;
    const int g    = lane >> 2, tg  = lane & 3;
    const int base = blockIdx.x * ROWS;
    const uint32_t sbase =
        (uint32_t)__cvta_generic_to_shared(sA);

    float acc[8][4];
#pragma unroll
    for (int i = 0; i < 8; ++i)
#pragma unroll
        for (int j = 0; j < 4; ++j) acc[i][j] = 0.f;

    // -- async gather of offset k into buffer (k&1) --
    auto issue = [&](int k) {
        const uint32_t dst0 = sbase + (uint32_t)(k & 1) * (ROWS * STRIDE * 4);
#pragma unroll
        for (int i = 0; i < ROWS * V / NTH; ++i) {
            const int e  = tid + i * NTH;
            const int r  = e / V;
            const int c4 = e - r * V;
            int idx = nbr ? __ldg(&nbr[(size_t)k * n + base + r]) : (base + r);
            const float* src = X + (size_t)(idx < 0 ? 0 : idx) * CIN + c4 * 4;
            cp16(dst0 + (uint32_t)(r * STRIDE + c4 * 4) * 4, src,
                 idx >= 0 ? 16 : 0);
        }
        cp_commit();
    };

    issue(0);
    const int r0 = wr * 16 + g;

    for (int k = 0; k < K; ++k) {
        cp_wait_all();
        __syncthreads();                 // buf (k+1)&1 free, buf k&1 ready
        if (k + 1 < K) issue(k + 1);     // overlap next gather with compute

        const float* A = sA + (k & 1) * (ROWS * STRIDE);
        const float2* Bp = reinterpret_cast<const float2*>(Wp)
                         + ((size_t)k * KC * 16 + wc * 8) * 32 + lane;
#pragma unroll 4
        for (int kc = 0; kc < KC; ++kc) {
            const int c0 = kc * 8 + tg;
            const uint32_t a0 = __float_as_uint(A[r0 * STRIDE + c0]);
            const uint32_t a1 = __float_as_uint(A[(r0 + 8) * STRIDE + c0]);
            const uint32_t a2 = __float_as_uint(A[r0 * STRIDE + c0 + 4]);
            const uint32_t a3 = __float_as_uint(A[(r0 + 8) * STRIDE + c0 + 4]);
            const float2* Bk = Bp + (size_t)kc * 16 * 32;
#pragma unroll
            for (int nt = 0; nt < 8; ++nt) {
                const float2 bv = __ldg(&Bk[nt * 32]);
                mma_tf32(acc[nt], a0, a1, a2, a3,
                         __float_as_uint(bv.x), __float_as_uint(bv.y));
            }
        }
    }

    // ---- store conv output ----
#pragma unroll
    for (int nt = 0; nt < 8; ++nt) {
        const int col  = wc * 64 + nt * 8 + 2 * tg;
        const int row  = base + r0;
        if (row < n)
            *reinterpret_cast<float2*>(out + (size_t)row * COUT + col) =
                make_float2(acc[nt][0], acc[nt][1]);
        if (row + 8 < n)
            *reinterpret_cast<float2*>(out + (size_t)(row + 8) * COUT + col) =
                make_float2(acc[nt][2], acc[nt][3]);
    }

    // ---- deterministic per-channel partials (Sx, Sx^2) ----
    float s[8][2], q[8][2];
#pragma unroll
    for (int nt = 0; nt < 8; ++nt) {
        s[nt][0] = acc[nt][0] + acc[nt][2];
        s[nt][1] = acc[nt][1] + acc[nt][3];
        q[nt][0] = acc[nt][0] * acc[nt][0] + acc[nt][2] * acc[nt][2];
        q[nt][1] = acc[nt][1] * acc[nt][1] + acc[nt][3] * acc[nt][3];
    }
#pragma unroll
    for (int off = 4; off <= 16; off <<= 1)      // reduce over g (8 lanes)
#pragma unroll
        for (int nt = 0; nt < 8; ++nt)
#pragma unroll
            for (int j = 0; j < 2; ++j) {
                s[nt][j] += __shfl_xor_sync(0xffffffffu, s[nt][j], off);
                q[nt][j] += __shfl_xor_sync(0xffffffffu, q[nt][j], off);
            }

    __syncthreads();                              // everyone done with sA
    float* sS = sA;                               // [2 wc][4 wr][64]
    float* sQ = sA + 512;
    if (lane < 4) {
#pragma unroll
        for (int nt = 0; nt < 8; ++nt) {
            const int col = nt * 8 + 2 * tg;
            sS[wc * 256 + wr * 64 + col]     = s[nt][0];
            sS[wc * 256 + wr * 64 + col + 1] = s[nt][1];
            sQ[wc * 256 + wr * 64 + col]     = q[nt][0];
            sQ[wc * 256 + wr * 64 + col + 1] = q[nt][1];
        }
    }
    __syncthreads();
    if (tid < 128) {
        const int c = tid;
        float t = 0.f;
#pragma unroll
        for (int w = 0; w < 4; ++w) t += sS[(c >> 6) * 256 + w * 64 + (c & 63)];
        partial[(size_t)blockIdx.x * 256 + c] = t;
    } else {
        const int c = tid - 128;
        float t = 0.f;
#pragma unroll
        for (int w = 0; w < 4; ++w) t += sQ[(c >> 6) * 256 + w * 64 + (c & 63)];
        partial[(size_t)blockIdx.x * 256 + 128 + c] = t;
    }
}

// ---------------------------------------------------------------------------
// Parallel BN finalize: 128 blocks (one per channel) x 256 threads.
// scale = gamma*rsqrt(var+eps), shift = beta - mean*scale.
// ---------------------------------------------------------------------------
__global__ void bn_finalize(const float* __restrict__ partial, int nb, int n,
                            const float* __restrict__ gamma,
                            const float* __restrict__ beta,
                            float* __restrict__ scale,
                            float* __restrict__ shift)
{
    const int c = blockIdx.x;
    const int t = threadIdx.x;
    __shared__ double rS[256], rQ[256];
    double S = 0.0, Q = 0.0;
    for (int b = t; b < nb; b += 256) {
        S += (double)partial[(size_t)b * 256 + c];
        Q += (double)partial[(size_t)b * 256 + 128 + c];
    }
    rS[t] = S; rQ[t] = Q;
    __syncthreads();
    for (int off = 128; off > 0; off >>= 1) {
        if (t < off) { rS[t] += rS[t + off]; rQ[t] += rQ[t + off]; }
        __syncthreads();
    }
    if (t == 0) {
        const double mean = rS[0] / n;
        const double var  = rQ[0] / n - mean * mean;
        const float  r    = rsqrtf((float)var + EPS_BN);
        const float  sc   = gamma[c] * r;
        scale[c] = sc;
        shift[c] = beta[c] - (float)mean * sc;
    }
}

// out = relu( h2*sc2 + sh2 + sk*scd + shd )
__global__ void final_kernel(const float* __restrict__ h2,
                             const float* __restrict__ sk,
                             const float* __restrict__ sc2,
                             const float* __restrict__ sh2,
                             const float* __restrict__ scd,
                             const float* __restrict__ shd,
                             float* __restrict__ out, int total4)
{
    const int i = blockIdx.x * blockDim.x + threadIdx.x;
    if (i >= total4) return;
    const int c4 = i & 31;
    const float4 a  = reinterpret_cast<const float4*>(h2)[i];
    const float4 b  = reinterpret_cast<const float4*>(sk)[i];
    const float4 s2 = reinterpret_cast<const float4*>(sc2)[c4];
    const float4 t2 = reinterpret_cast<const float4*>(sh2)[c4];
    const float4 sd = reinterpret_cast<const float4*>(scd)[c4];
    const float4 td = reinterpret_cast<const float4*>(shd)[c4];
    float4 v;
    v.x = fmaxf(0.f, fmaf(a.x, s2.x, t2.x) + fmaf(b.x, sd.x, td.x));
    v.y = fmaxf(0.f, fmaf(a.y, s2.y, t2.y) + fmaf(b.y, sd.y, td.y));
    v.z = fmaxf(0.f, fmaf(a.z, s2.z, t2.z) + fmaf(b.z, sd.z, td.z));
    v.w = fmaxf(0.f, fmaf(a.w, s2.w, t2.w) + fmaf(b.w, sd.w, td.w));
    reinterpret_cast<float4*>(out)[i] = v;
}

// ---------------------------------------------------------------------------
extern "C" void kernel_launch(void* const* d_in, const int* in_sizes, int n_in,
                              void* d_out, int out_size)
{
    const float* feats = (const float*)d_in[0];
    const int*   nbr1  = (const int*)  d_in[1];
    const int*   nbr2  = (const int*)  d_in[2];
    const float* W1    = (const float*)d_in[3];
    const float* W2    = (const float*)d_in[4];
    const float* Wd    = (const float*)d_in[5];
    const float* g1    = (const float*)d_in[6];
    const float* b1    = (const float*)d_in[7];
    const float* g2    = (const float*)d_in[8];
    const float* b2    = (const float*)d_in[9];
    const float* gd    = (const float*)d_in[10];
    const float* bd    = (const float*)d_in[11];
    float* out = (float*)d_out;

    const int n  = in_sizes[0] / 64;      // 200000
    const int K  = in_sizes[1] / n;       // 27
    const int nb = (n + ROWS - 1) / ROWS; // 3125

    float *h1, *h1t, *h2, *sk, *xt, *wp1, *wp2, *wpd, *p1, *p2, *pd;
    float *sc1, *sh1, *sc2, *sh2, *scd, *shd;
    cudaGetSymbolAddress((void**)&h1,  g_h1);
    cudaGetSymbolAddress((void**)&h1t, g_h1t);
    cudaGetSymbolAddress((void**)&h2,  g_h2);
    cudaGetSymbolAddress((void**)&sk,  g_sk);
    cudaGetSymbolAddress((void**)&xt,  g_xt);
    cudaGetSymbolAddress((void**)&wp1, g_wp1);
    cudaGetSymbolAddress((void**)&wp2, g_wp2);
    cudaGetSymbolAddress((void**)&wpd, g_wpd);
    cudaGetSymbolAddress((void**)&p1,  g_part1);
    cudaGetSymbolAddress((void**)&p2,  g_part2);
    cudaGetSymbolAddress((void**)&pd,  g_partd);
    cudaGetSymbolAddress((void**)&sc1, g_sc1);
    cudaGetSymbolAddress((void**)&sh1, g_sh1);
    cudaGetSymbolAddress((void**)&sc2, g_sc2);
    cudaGetSymbolAddress((void**)&sh2, g_sh2);
    cudaGetSymbolAddress((void**)&scd, g_scd);
    cudaGetSymbolAddress((void**)&shd, g_shd);

    const int smem64  = 2 * ROWS * (64 + 4)  * 4;   // 34816 B
    const int smem128 = 2 * ROWS * (128 + 4) * 4;   // 67584 B
    static bool attr_set = false;
    if (!attr_set) {
        cudaFuncSetAttribute(conv_mma<64>,
            cudaFuncAttributeMaxDynamicSharedMemorySize, smem64);
        cudaFuncSetAttribute(conv_mma<128>,
            cudaFuncAttributeMaxDynamicSharedMemorySize, smem128);
        attr_set = true;
    }

    // ---- prep: tf32-round feats, reorder weights into fragment order ----
    const int xt4 = n * (64 / 4);
    cvt_kernel<<<(xt4 + NTH - 1) / NTH, NTH>>>(feats, xt, xt4);
    {
        int t1 = K * (64 / 8)  * 16 * 32;
        int t2 = K * (128 / 8) * 16 * 32;
        int td = 1 * (64 / 8)  * 16 * 32;
        prep_w<<<(t1 + NTH - 1) / NTH, NTH>>>(W1, wp1, K, 64);
        prep_w<<<(t2 + NTH - 1) / NTH, NTH>>>(W2, wp2, K, 128);
        prep_w<<<(td + NTH - 1) / NTH, NTH>>>(Wd, wpd, 1, 64);
    }

    // conv1 + BN1 partials
    conv_mma<64><<<nb, NTH, smem64>>>(xt, wp1, nbr1, K, n, h1, p1);
    // skip (identity gather, K=1) + BNd partials
    conv_mma<64><<<nb, NTH, smem64>>>(xt, wpd, nullptr, 1, n, sk, pd);
    bn_finalize<<<128, 256>>>(p1, nb, n, g1, b1, sc1, sh1);
    bn_finalize<<<128, 256>>>(pd, nb, n, gd, bd, scd, shd);
    // h1t = tf32(relu(BN1(h1)))
    const int t4 = n * (COUT / 4);
    bn_relu_cvt<<<(t4 + NTH - 1) / NTH, NTH>>>(h1, sc1, sh1, h1t, t4);
    // conv2 + BN2 partials
    conv_mma<128><<<nb, NTH, smem128>>>(h1t, wp2, nbr2, K, n, h2, p2);
    bn_finalize<<<128, 256>>>(p2, nb, n, g2, b2, sc2, sh2);
    // out = relu(BN2(h2) + BNd(sk))
    final_kernel<<<(t4 + NTH - 1) / NTH, NTH>>>(h2, sk, sc2, sh2,
                                                scd, shd, out, t4);
}